// round 2
// baseline (speedup 1.0000x reference)
#include <cuda_runtime.h>
#include <stdint.h>

// CornerActivationB: out[b, g*16+d] = bilinear interp of params[g, 0..3, d]
//   u_i = (clip(x_i,-1,1)+1)*0.5
//   coef(j0,j1) = (j0? u0 : 1-u0) * (j1? u1 : 1-u1), param index 2*j0+j1
//
// BATCH=8192, GROUPS=512, OUT_DIM=16, ARITY=2.
// X: [8192, 1024] f32, params: [512, 4, 16] f32, out: [8192, 8192] f32.
//
// Thread layout: 256 threads/block. tid -> (g_local = tid>>2 in [0,64),
// q = tid&3 covering d in [4q, 4q+4)). Each thread keeps its 4 param float4s
// in registers and loops over B_TILE=32 batch rows. Per-warp store per row:
// 512 contiguous bytes (coalesced STG.128).

#define GROUPS   512
#define OUT_DIM  16
#define BATCH    8192
#define GDIM     (GROUPS * OUT_DIM)   // 8192 floats per output row
#define XDIM     (GROUPS * 2)         // 1024 floats per input row
#define G_TILE   64
#define B_TILE   32

__global__ void __launch_bounds__(256, 4)
corner_act_kernel(const float* __restrict__ X,
                  const float* __restrict__ P,
                  float* __restrict__ out)
{
    const int tid   = threadIdx.x;
    const int q     = tid & 3;           // which d-quad (0..3)
    const int gl    = tid >> 2;          // group within tile (0..63)
    const int gtile = blockIdx.x & (GROUPS / G_TILE - 1);   // 0..7
    const int btile = blockIdx.x >> 3;                       // 0..255
    const int g     = gtile * G_TILE + gl;
    const int b0    = btile * B_TILE;

    // params[g, j, d]: float index g*64 + j*16 + d -> float4 index g*16 + j*4 + q
    const float4* Pg = reinterpret_cast<const float4*>(P) + (size_t)g * 16;
    const float4 p0 = Pg[0 * 4 + q];
    const float4 p1 = Pg[1 * 4 + q];
    const float4 p2 = Pg[2 * 4 + q];
    const float4 p3 = Pg[3 * 4 + q];

    const float2* Xb = reinterpret_cast<const float2*>(X + (size_t)b0 * XDIM) + g;
    float*        Ob = out + (size_t)b0 * GDIM + (size_t)g * OUT_DIM + q * 4;

    #pragma unroll 4
    for (int r = 0; r < B_TILE; ++r) {
        float2 xv = __ldg(Xb + (size_t)r * (XDIM / 2));
        float u0 = (fminf(fmaxf(xv.x, -1.0f), 1.0f) + 1.0f) * 0.5f;
        float u1 = (fminf(fmaxf(xv.y, -1.0f), 1.0f) + 1.0f) * 0.5f;
        float v0 = 1.0f - u0;
        float v1 = 1.0f - u1;
        float c00 = v0 * v1;
        float c01 = v0 * u1;
        float c10 = u0 * v1;
        float c11 = u0 * u1;

        float4 o;
        o.x = c00 * p0.x + c01 * p1.x + c10 * p2.x + c11 * p3.x;
        o.y = c00 * p0.y + c01 * p1.y + c10 * p2.y + c11 * p3.y;
        o.z = c00 * p0.z + c01 * p1.z + c10 * p2.z + c11 * p3.z;
        o.w = c00 * p0.w + c01 * p1.w + c10 * p2.w + c11 * p3.w;

        *reinterpret_cast<float4*>(Ob + (size_t)r * GDIM) = o;
    }
}

extern "C" void kernel_launch(void* const* d_in, const int* in_sizes, int n_in,
                              void* d_out, int out_size)
{
    const float* X = (const float*)d_in[0];
    const float* P = (const float*)d_in[1];
    float* out = (float*)d_out;

    dim3 grid((GROUPS / G_TILE) * (BATCH / B_TILE));  // 8 * 256 = 2048 blocks
    dim3 block(256);
    corner_act_kernel<<<grid, block>>>(X, P, out);
}